// round 11
// baseline (speedup 1.0000x reference)
#include <cuda_runtime.h>
#include <cuda_bf16.h>

#define MAX_LEN_SEQ 2048
#define T_PAD       2176
#define MIN_SEG     32
#define S_          65
#define B_          16
#define D_          128
#define R_          1040
#define W_          256

__device__ volatile int g_flag = 0;   // release flag: metadata ready
__device__ int g_done = 0;            // finished-block counter (self-reset)
__device__ int g_offset[R_];
__device__ int g_rowstart[R_ + 1];
__device__ int g_L;

// ---------------------------------------------------------------------------
// Single fused kernel.
// Block 0 prologue: per-row masked-prefix counts (binary search on the
// reference's exact fp32 expression floorf(w/sc) vs float(lim)), per-batch
// segment offsets, global exclusive scan -> g_rowstart / g_L. Published via
// threadfence + volatile flag. Other blocks spin (thread 0 + nanosleep).
// Then every block gathers: one warp per output row, inverting the global
// compaction with a 2-round warp-parallel search. Last block to finish
// resets the flag so graph replays are deterministic.
// ---------------------------------------------------------------------------
__global__ __launch_bounds__(256) void k_fused(const float* __restrict__ x,
                                               const float* __restrict__ scales,
                                               const int*   __restrict__ len_seq,
                                               const int*   __restrict__ len_seg_raw,
                                               float* __restrict__ out) {
    __shared__ int sh_len[R_];
    __shared__ int sh_off[R_];
    __shared__ int sh_cnt[R_];
    __shared__ int sh_lseq[B_];
    int tid = threadIdx.x;

    if (blockIdx.x == 0) {
        // ---- load inputs ----
        for (int i = tid; i < R_; i += 256) sh_len[i] = len_seg_raw[i] + MIN_SEG;
        if (tid < B_) sh_lseq[tid] = len_seq[tid];
        __syncthreads();
        // ---- per-batch exclusive offsets (16 serial lane-scans, 65 each) ----
        if (tid < B_) {
            int base = tid * S_;
            int off = 0;
            #pragma unroll 5
            for (int j = 0; j < S_; j++) {
                sh_off[base + j]   = off;
                g_offset[base + j] = off;
                off += sh_len[base + j];
            }
        }
        __syncthreads();
        // ---- per-row masked count (prefix length in w) ----
        for (int r = tid; r < R_; r += 256) {
            int b = r / S_;
            int lim = min(sh_len[r] - 1, sh_lseq[b] - 1 - sh_off[r]);
            float sc = __ldg(&scales[r]) + 0.5f;
            float limf = (float)lim;
            int lo = 0, hi = W_;
            #pragma unroll 1
            while (lo < hi) {
                int mid = (lo + hi) >> 1;
                if (floorf((float)mid / sc) < limf) lo = mid + 1; else hi = mid;
            }
            sh_cnt[r] = lo;    // lo==0 automatically when lim<=0
        }
        __syncthreads();
        // ---- exclusive scan of counts -> g_rowstart, total, L ----
        if (tid < 32) {
            const int CH = 33;
            int base = tid * CH;
            int s = 0;
            #pragma unroll
            for (int j = 0; j < CH; j++) {
                int i = base + j;
                if (i < R_) s += sh_cnt[i];
            }
            int incl = s;
            #pragma unroll
            for (int d = 1; d < 32; d <<= 1) {
                int v = __shfl_up_sync(0xffffffffu, incl, d);
                if (tid >= d) incl += v;
            }
            int run = incl - s;
            #pragma unroll
            for (int j = 0; j < CH; j++) {
                int i = base + j;
                if (i < R_) { g_rowstart[i] = run; run += sh_cnt[i]; }
            }
            if (tid == 31) {
                g_rowstart[R_] = run;
                g_L = run / B_;
            }
        }
        // ---- publish ----
        __threadfence();
        __syncthreads();
        if (tid == 0) g_flag = 1;
    } else {
        // ---- wait for metadata ----
        if (tid == 0) {
            while (g_flag == 0) __nanosleep(64);
        }
        __syncthreads();
        __threadfence();
    }

    // ------------------- gather: one warp per output row -------------------
    {
        int warp = blockIdx.x * 8 + (threadIdx.x >> 5);
        int lane = threadIdx.x & 31;
        int b = warp >> 11;                // / 2048
        int t = warp & (MAX_LEN_SEQ - 1);

        float4* orow = reinterpret_cast<float4*>(out + (size_t)warp * D_);
        int L = g_L;
        if (t >= L) {
            orow[lane] = make_float4(0.f, 0.f, 0.f, 0.f);
        } else {
            int g = b * L + t;
            // warp-parallel 2-round search of g_rowstart:
            // round 1: coarse probe at stride 33 (lane*33 in [0,1023])
            int i1 = lane * 33;
            bool p1 = (__ldg(&g_rowstart[i1]) <= g);          // lane 0 always true
            unsigned m1 = __ballot_sync(0xffffffffu, p1);
            int base = (31 - __clz(m1)) * 33;
            // round 2: probe base+1 .. base+32; prefix of trues gives offset
            int i2 = base + 1 + lane;
            bool p2 = (i2 <= R_) && (__ldg(&g_rowstart[i2]) <= g);
            unsigned m2 = __ballot_sync(0xffffffffu, p2);
            int r = base + __popc(m2);

            int w = g - __ldg(&g_rowstart[r]);
            float sc = __ldg(&scales[r]) + 0.5f;
            float idx_scaled = (float)w / sc;
            float idx_fl = floorf(idx_scaled);
            float lam = idx_scaled - idx_fl;
            int i_fl = (int)idx_fl + __ldg(&g_offset[r]);
            if (i_fl > T_PAD - 1) i_fl = T_PAD - 1;
            int i_cl = min(i_fl + 1, T_PAD - 1);
            int bsrc = r / S_;

            const float4* pa = reinterpret_cast<const float4*>(x + ((size_t)bsrc * T_PAD + i_fl) * D_);
            const float4* pc = reinterpret_cast<const float4*>(x + ((size_t)bsrc * T_PAD + i_cl) * D_);
            float4 va = __ldg(&pa[lane]);
            float4 vc = __ldg(&pc[lane]);
            float om = 1.0f - lam;
            float4 vy;
            vy.x = om * va.x + lam * vc.x;
            vy.y = om * va.y + lam * vc.y;
            vy.z = om * va.z + lam * vc.z;
            vy.w = om * va.w + lam * vc.w;
            orow[lane] = vy;
        }
    }

    // ---- self-reset for next graph replay (last block clears the flag) ----
    if (tid == 0) {
        int v = atomicAdd(&g_done, 1);
        if (v == (int)gridDim.x - 1) {
            g_done = 0;
            __threadfence();
            g_flag = 0;
        }
    }
}

extern "C" void kernel_launch(void* const* d_in, const int* in_sizes, int n_in,
                              void* d_out, int out_size) {
    const float* x           = (const float*)d_in[0];
    const float* scales      = (const float*)d_in[1];
    const int*   len_seq     = (const int*)d_in[2];
    const int*   len_seg_raw = (const int*)d_in[3];
    float* out = (float*)d_out;

    k_fused<<<(B_ * MAX_LEN_SEQ) / 8, 256>>>(x, scales, len_seq, len_seg_raw, out);
}

// round 12
// speedup vs baseline: 1.7210x; 1.7210x over previous
#include <cuda_runtime.h>
#include <cuda_bf16.h>

#define MAX_LEN_SEQ 2048
#define T_PAD       2176
#define MIN_SEG     32
#define S_          65
#define B_          16
#define D_          128
#define R_          1040
#define W_          256

__device__ int g_offset[R_];
__device__ int g_rowstart[R_ + 1];
__device__ int g_L;

// ---------------------------------------------------------------------------
// Kernel A: single block, 1024 threads. Computes per-row masked-prefix
// counts, per-batch segment offsets, and the global exclusive scan.
//
// Count logic: the reference mask for row r is a prefix in w:
//   mask(w) = floor(w/sc) < len_seg-1  AND  floor(w/sc)+off < len_seq-1
// Both limits are small exact-in-fp32 integers, so with lim = min(...):
//   mask(w) ⟺ RN(w/sc) < float(lim)        (floor(v) < L ⟺ v < L, L integer)
// count = first w with RN(w/sc) >= limf. Seed with ceilf(sc*limf) and fix up
// with the EXACT fp32 predicate (1-2 iterations), so results are bit-identical
// to the reference's mask.
// ---------------------------------------------------------------------------
__global__ __launch_bounds__(1024) void k_meta(const float* __restrict__ scales,
                                               const int*   __restrict__ len_seq,
                                               const int*   __restrict__ len_seg_raw) {
    __shared__ int sh_len[R_];
    __shared__ int sh_off[R_];
    __shared__ int sh_cnt[R_];
    __shared__ int sh_lseq[B_];
    int tid  = threadIdx.x;
    int wid  = tid >> 5;
    int lane = tid & 31;

    if (tid < R_) sh_len[tid] = len_seg_raw[tid] + MIN_SEG;
    if (tid >= 1024 - 16) { /* nothing */ }
    if (tid < 16) sh_len[1024 + tid] = len_seg_raw[1024 + tid] + MIN_SEG;
    if (tid < B_) sh_lseq[tid] = len_seq[tid];
    __syncthreads();

    // ---- per-batch exclusive offsets via warp shuffle scans (warp b = batch b)
    if (wid < B_) {
        int base = wid * S_;
        int v0 = sh_len[base + lane];          // elems 0..31
        int v1 = sh_len[base + 32 + lane];     // elems 32..63 (base+63 <= R_-2)
        int s0 = v0, s1 = v1;
        #pragma unroll
        for (int d = 1; d < 32; d <<= 1) {
            int u0 = __shfl_up_sync(0xffffffffu, s0, d);
            int u1 = __shfl_up_sync(0xffffffffu, s1, d);
            if (lane >= d) { s0 += u0; s1 += u1; }
        }
        int tot0 = __shfl_sync(0xffffffffu, s0, 31);
        int tot1 = __shfl_sync(0xffffffffu, s1, 31);
        int e0 = s0 - v0;                       // exclusive
        int e1 = tot0 + (s1 - v1);
        sh_off[base + lane]      = e0;
        sh_off[base + 32 + lane] = e1;
        g_offset[base + lane]      = e0;
        g_offset[base + 32 + lane] = e1;
        if (lane == 0) {
            sh_off[base + 64]   = tot0 + tot1;
            g_offset[base + 64] = tot0 + tot1;
        }
    }
    __syncthreads();

    // ---- per-row counts (candidate + exact-predicate fix-up)
    #pragma unroll
    for (int r = tid; r < R_; r += 1024) {
        int b   = r / S_;
        int lim = min(sh_len[r] - 1, sh_lseq[b] - 1 - sh_off[r]);
        int cnt = 0;
        if (lim > 0) {
            float sc   = __ldg(&scales[r]) + 0.5f;
            float limf = (float)lim;
            int cand = (int)ceilf(sc * limf);
            cand = max(0, min(cand, W_));
            while (cand < W_ && ((float)cand / sc) < limf) cand++;
            while (cand > 0 && ((float)(cand - 1) / sc) >= limf) cand--;
            cnt = cand;
        }
        sh_cnt[r] = cnt;
    }
    __syncthreads();

    // ---- exclusive scan of 1040 counts (32 lanes x 33-chunk, then shuffle)
    if (tid < 32) {
        const int CH = 33;
        int base = tid * CH;
        int s = 0;
        #pragma unroll
        for (int j = 0; j < CH; j++) {
            int i = base + j;
            if (i < R_) s += sh_cnt[i];
        }
        int incl = s;
        #pragma unroll
        for (int d = 1; d < 32; d <<= 1) {
            int v = __shfl_up_sync(0xffffffffu, incl, d);
            if (tid >= d) incl += v;
        }
        int run = incl - s;
        #pragma unroll
        for (int j = 0; j < CH; j++) {
            int i = base + j;
            if (i < R_) { g_rowstart[i] = run; run += sh_cnt[i]; }
        }
        if (tid == 31) {
            g_rowstart[R_] = run;
            g_L = run / B_;
        }
    }
}

// ---------------------------------------------------------------------------
// Kernel B: one warp per output row (b, t). Inverts the global compaction
// with a 2-round warp-parallel search (2 dependent loads), then float4 lerp.
// ---------------------------------------------------------------------------
__global__ __launch_bounds__(256) void k_gather(const float* __restrict__ x,
                                                const float* __restrict__ scales,
                                                float* __restrict__ out) {
    int warp = blockIdx.x * 8 + (threadIdx.x >> 5);
    int lane = threadIdx.x & 31;
    int b = warp >> 11;
    int t = warp & (MAX_LEN_SEQ - 1);

    float4* orow = reinterpret_cast<float4*>(out + (size_t)warp * D_);
    int L = g_L;
    if (t >= L) { orow[lane] = make_float4(0.f, 0.f, 0.f, 0.f); return; }

    int g = b * L + t;
    // round 1: coarse probe at stride 33
    int i1 = lane * 33;
    bool p1 = (__ldg(&g_rowstart[i1]) <= g);
    unsigned m1 = __ballot_sync(0xffffffffu, p1);
    int base = (31 - __clz(m1)) * 33;
    // round 2: probe base+1 .. base+32
    int i2 = base + 1 + lane;
    bool p2 = (i2 <= R_) && (__ldg(&g_rowstart[i2]) <= g);
    unsigned m2 = __ballot_sync(0xffffffffu, p2);
    int r = base + __popc(m2);

    int w = g - __ldg(&g_rowstart[r]);
    float sc = __ldg(&scales[r]) + 0.5f;
    float idx_scaled = (float)w / sc;
    float idx_fl = floorf(idx_scaled);
    float lam = idx_scaled - idx_fl;
    int i_fl = (int)idx_fl + __ldg(&g_offset[r]);
    if (i_fl > T_PAD - 1) i_fl = T_PAD - 1;
    int i_cl = min(i_fl + 1, T_PAD - 1);
    int bsrc = r / S_;

    const float4* pa = reinterpret_cast<const float4*>(x + ((size_t)bsrc * T_PAD + i_fl) * D_);
    const float4* pc = reinterpret_cast<const float4*>(x + ((size_t)bsrc * T_PAD + i_cl) * D_);
    float4 va = __ldg(&pa[lane]);
    float4 vc = __ldg(&pc[lane]);
    float om = 1.0f - lam;
    float4 vy;
    vy.x = om * va.x + lam * vc.x;
    vy.y = om * va.y + lam * vc.y;
    vy.z = om * va.z + lam * vc.z;
    vy.w = om * va.w + lam * vc.w;
    orow[lane] = vy;
}

extern "C" void kernel_launch(void* const* d_in, const int* in_sizes, int n_in,
                              void* d_out, int out_size) {
    const float* x           = (const float*)d_in[0];
    const float* scales      = (const float*)d_in[1];
    const int*   len_seq     = (const int*)d_in[2];
    const int*   len_seg_raw = (const int*)d_in[3];
    float* out = (float*)d_out;

    k_meta<<<1, 1024>>>(scales, len_seq, len_seg_raw);
    k_gather<<<(B_ * MAX_LEN_SEQ) / 8, 256>>>(x, scales, out);
}